// round 5
// baseline (speedup 1.0000x reference)
#include <cuda_runtime.h>
#include <cstdint>

// Problem constants
#define NIMG 256          // B*L
#define CCH  64           // channels
#define HW   32           // height = width
#define IMGSZ (CCH*HW*HW) // 65536 floats per image
#define NODES 256

// Scratch (device globals: allocation-free per harness rules)
__device__ float g_xs[NIMG * IMGSZ];   // aggregated x (tf32-rounded values)
__device__ float g_h [NIMG * IMGSZ];   // hidden (tf32-rounded values)
__device__ float g_hs[NIMG * IMGSZ];   // aggregated hidden (tf32-rounded)
__device__ int   g_nbr[NODES * 8];
__device__ int   g_cnt[NODES];
__device__ int   g_mode;               // 0=u8 mask, 1=u16, 2=u32/f32

// Pre-transformed weights, tf32 bits:
// [chunk32 = layer*16 + half*8 + cc][tap9][qid8][q4][nt pad 10] uint2
#define W_CHUNK  2880                  // uint2 per chunk (9*8*4*10)
#define W_TAP_U4 160                   // uint4 per tap block
#define WPREP_TOTAL (32 * W_CHUNK)
__device__ uint2 g_wprep[WPREP_TOTAL];

// patch layout: [c8][row10][36 floats]; word col 1+gx; halo cols stay zero
#define P_CSTR 360
#define P_RSTR 36
#define P_ELEMS 2880    // floats per buffer
#define NSTAGE 3
#define SMEM_BYTES (NSTAGE*(P_ELEMS*4 + W_CHUNK*8))   // 3*34560 = 103680

__device__ __forceinline__ uint32_t f2tf32(float f) {
    uint32_t u;
    asm("cvt.rna.tf32.f32 %0, %1;" : "=r"(u) : "f"(f));
    return u;
}

__device__ __forceinline__ void cp16(void* s, const void* g) {
    uint32_t sa = (uint32_t)__cvta_generic_to_shared(s);
    asm volatile("cp.async.cg.shared.global [%0], [%1], 16;" :: "r"(sa), "l"(g));
}

__device__ __forceinline__ void cp4(void* s, const void* g) {
    uint32_t sa = (uint32_t)__cvta_generic_to_shared(s);
    asm volatile("cp.async.ca.shared.global [%0], [%1], 4;" :: "r"(sa), "l"(g));
}

__device__ __forceinline__ void mma_tf32(float& d0, float& d1, float& d2, float& d3,
                                         uint32_t a0, uint32_t a1, uint32_t a2, uint32_t a3,
                                         uint32_t b0, uint32_t b1) {
    asm volatile(
        "mma.sync.aligned.m16n8k8.row.col.f32.tf32.tf32.f32 "
        "{%0,%1,%2,%3},{%4,%5,%6,%7},{%8,%9},{%0,%1,%2,%3};"
        : "+f"(d0), "+f"(d1), "+f"(d2), "+f"(d3)
        : "r"(a0), "r"(a1), "r"(a2), "r"(a3), "r"(b0), "r"(b1));
}

// ---------------------------------------------------------------------------
// Mask dtype detection + neighbor list build (unchanged, correct)
// ---------------------------------------------------------------------------
__global__ void detect_kernel(const void* m) {
    __shared__ int bad;
    int row = threadIdx.x;
    if (row == 0) bad = 0;
    __syncthreads();
    {
        const unsigned char* p = (const unsigned char*)m + row * 64;
        int c = 0;
        for (int j = 0; j < 64; j++) c += (p[j] != 0);
        if (c != 4) atomicOr(&bad, 1);
    }
    __syncthreads();
    int ok8 = !bad;
    __syncthreads();
    if (row == 0) bad = 0;
    __syncthreads();
    if (!ok8) {
        const unsigned short* p = (const unsigned short*)m + row * 64;
        int c = 0;
        for (int j = 0; j < 64; j++) c += (p[j] != 0);
        if (c != 4) atomicOr(&bad, 1);
    }
    __syncthreads();
    int ok16 = (!ok8) && (!bad);
    if (row == 0) g_mode = ok8 ? 0 : (ok16 ? 1 : 2);
}

__global__ void build_kernel(const void* m) {
    int row = threadIdx.x;
    if (row >= NODES) return;
    int mode = g_mode;
    int base = (row >> 6) << 6;
    int cnt = 0;
    if (mode == 0) {
        const unsigned char* p = (const unsigned char*)m + row * 64;
        for (int j = 0; j < 64; j++)
            if (p[j]) { if (cnt < 8) g_nbr[row * 8 + cnt] = base + j; cnt++; }
    } else if (mode == 1) {
        const unsigned short* p = (const unsigned short*)m + row * 64;
        for (int j = 0; j < 64; j++)
            if (p[j]) { if (cnt < 8) g_nbr[row * 8 + cnt] = base + j; cnt++; }
    } else {
        const unsigned int* p = (const unsigned int*)m + row * 64;
        for (int j = 0; j < 64; j++)
            if (p[j]) { if (cnt < 8) g_nbr[row * 8 + cnt] = base + j; cnt++; }
    }
    g_cnt[row] = cnt;
}

// ---------------------------------------------------------------------------
// Weight pre-transform into [chunk][tap][qid][q][nt pad10] uint2 layout
// ---------------------------------------------------------------------------
__global__ void prep_weights(const float* __restrict__ w_x0, const float* __restrict__ w_n0,
                             const float* __restrict__ w_x1, const float* __restrict__ w_n1) {
    int e = blockIdx.x * 256 + threadIdx.x;
    if (e >= WPREP_TOTAL) return;
    int nt = e % 10; int t = e / 10;
    int q   = t & 3;  t >>= 2;
    int qid = t & 7;  t >>= 3;
    int tap = t % 9;  t /= 9;        // t = chunk id 0..31
    int cc   = t & 7;
    int half = (t >> 3) & 1;
    int layer = t >> 4;
    const float* w = layer ? (half ? w_n1 : w_x1) : (half ? w_n0 : w_x0);
    uint2 v = make_uint2(0u, 0u);
    if (nt < 8) {
        int co = nt * 8 + qid;
        int cb = cc * 8;
        v.x = f2tf32(w[co * 576 + (cb + q) * 9 + tap]);
        v.y = f2tf32(w[co * 576 + (cb + q + 4) * 9 + tap]);
    }
    g_wprep[e] = v;
}

// ---------------------------------------------------------------------------
// Neighbor aggregation; output rounded to tf32 values (conv A operand ready)
// ---------------------------------------------------------------------------
__global__ void agg_kernel(const float* __restrict__ src, float* __restrict__ dst) {
    int node = blockIdx.x;
    int cnt = g_cnt[node];
    if (cnt > 8) cnt = 8;
    int i0 = blockIdx.y * blockDim.x + threadIdx.x;
    int stride = gridDim.y * blockDim.x;
    const float4* s4 = (const float4*)src;
    float4* d4 = (float4*)dst;
    int nb[8];
    for (int k = 0; k < cnt; k++) nb[k] = g_nbr[node * 8 + k];
    const int n4 = IMGSZ / 4;
    for (int i = i0; i < n4; i += stride) {
        float4 acc = make_float4(0.f, 0.f, 0.f, 0.f);
        for (int k = 0; k < cnt; k++) {
            float4 v = s4[nb[k] * n4 + i];
            acc.x += v.x; acc.y += v.y; acc.z += v.z; acc.w += v.w;
        }
        acc.x = __uint_as_float(f2tf32(acc.x));
        acc.y = __uint_as_float(f2tf32(acc.y));
        acc.z = __uint_as_float(f2tf32(acc.z));
        acc.w = __uint_as_float(f2tf32(acc.w));
        d4[node * n4 + i] = acc;
    }
}

// ---------------------------------------------------------------------------
// Conv: 3-stage cp.async pipeline, LDS.128 B-frags, optional in-loop cvt
// ---------------------------------------------------------------------------
__device__ __forceinline__ void issue_chunk(float* pat, uint4* wdst,
                                            const uint2* __restrict__ wsrc,
                                            const float* __restrict__ inp,
                                            int n, int cb, int y0, int tid) {
    const uint4* ws = (const uint4*)wsrc;
#pragma unroll
    for (int k = 0; k < 6; k++) {
        int idx = tid + k * 256;
        if (idx < W_CHUNK / 2) cp16(wdst + idx, ws + idx);
    }
#pragma unroll
    for (int k = 0; k < 10; k++) {
        int i = tid + k * 256;
        int col = i & 31;
        int r = (i >> 5) % 10;
        int c = i / 320;
        int gy = y0 + r - 1;
        if (gy >= 0 && gy < HW)
            cp4(pat + c * P_CSTR + r * P_RSTR + 1 + col,
                inp + ((n * CCH + c + cb) * HW + gy) * HW + col);
    }
    asm volatile("cp.async.commit_group;" ::: "memory");
}

template <bool CVT>
__device__ __forceinline__ void compute_chunk(const float* __restrict__ pat,
                                              const uint4* __restrict__ wq,
                                              int w, int qid, int q, int wtbase,
                                              float (&acc)[2][8][4]) {
    uint4 bb[2][4];
#pragma unroll
    for (int j = 0; j < 4; j++) bb[0][j] = wq[wtbase + j];

#pragma unroll
    for (int tap = 0; tap < 9; tap++) {
        const int ty = tap / 3, tx = tap % 3;
        const int cur = tap & 1;
        if (tap < 8) {
            const uint4* wn = wq + (tap + 1) * W_TAP_U4 + wtbase;
#pragma unroll
            for (int j = 0; j < 4; j++) bb[1 - cur][j] = wn[j];
        }
        const int ro = (w + ty) * P_RSTR + qid + tx;
        const int blo = q * P_CSTR + ro;
        const int bhi = (q + 4) * P_CSTR + ro;
        uint32_t a[2][4];
#pragma unroll
        for (int mt = 0; mt < 2; mt++) {
            const int xo = mt * 16;
            if (CVT) {
                a[mt][0] = f2tf32(pat[blo + xo]);
                a[mt][1] = f2tf32(pat[blo + xo + 8]);
                a[mt][2] = f2tf32(pat[bhi + xo]);
                a[mt][3] = f2tf32(pat[bhi + xo + 8]);
            } else {
                a[mt][0] = __float_as_uint(pat[blo + xo]);
                a[mt][1] = __float_as_uint(pat[blo + xo + 8]);
                a[mt][2] = __float_as_uint(pat[bhi + xo]);
                a[mt][3] = __float_as_uint(pat[bhi + xo + 8]);
            }
        }
        const uint32_t* b = (const uint32_t*)bb[cur];
#pragma unroll
        for (int mt = 0; mt < 2; mt++)
#pragma unroll
            for (int nt = 0; nt < 8; nt++)
                mma_tf32(acc[mt][nt][0], acc[mt][nt][1],
                         acc[mt][nt][2], acc[mt][nt][3],
                         a[mt][0], a[mt][1], a[mt][2], a[mt][3],
                         b[2 * nt], b[2 * nt + 1]);
    }
}

__global__ __launch_bounds__(256, 2)
void conv_kernel(const float* __restrict__ inA, const float* __restrict__ inB,
                 const uint2* __restrict__ wprep,
                 const float* __restrict__ bA,  const float* __restrict__ bB,
                 const float* __restrict__ resid, float* __restrict__ out,
                 int cvtHalf0, int roundOut) {
    extern __shared__ uint8_t smem[];
    float* patB[NSTAGE];
    uint4* wsmB[NSTAGE];
    patB[0] = (float*)smem;
    patB[1] = patB[0] + P_ELEMS;
    patB[2] = patB[1] + P_ELEMS;
    wsmB[0] = (uint4*)(patB[2] + P_ELEMS);
    wsmB[1] = wsmB[0] + W_CHUNK / 2;
    wsmB[2] = wsmB[1] + W_CHUNK / 2;

    const int n = blockIdx.y;
    const int rb = blockIdx.x;
    const int tid = threadIdx.x;
    const int w = tid >> 5;
    const int lane = tid & 31;
    const int qid = lane >> 2;
    const int q = lane & 3;
    const int y0 = rb * 8;

    // zero all patch buffers once (halo cells never overwritten later)
#pragma unroll
    for (int k = 0; k < 34; k++) {
        int i = tid + k * 256;
        if (i < NSTAGE * P_ELEMS) patB[0][i] = 0.f;
    }
    __syncthreads();

    float acc[2][8][4];
#pragma unroll
    for (int mt = 0; mt < 2; mt++)
#pragma unroll
        for (int nt = 0; nt < 8; nt++)
#pragma unroll
            for (int r = 0; r < 4; r++) acc[mt][nt][r] = 0.f;

    // prolog: chunks 0 and 1 in flight
    issue_chunk(patB[0], wsmB[0], wprep, inA, n, 0, y0, tid);
    issue_chunk(patB[1], wsmB[1], wprep + W_CHUNK, inA, n, 8, y0, tid);
    asm volatile("cp.async.wait_group 1;" ::: "memory");   // chunk 0 resident
    __syncthreads();

    const int wtbase = (qid * 4 + q) * 5;

    for (int it = 0; it < 16; ++it) {
        const int p = it % NSTAGE;
        if (it < 14) {
            const int jt = it + 2;
            issue_chunk(patB[jt % NSTAGE], wsmB[jt % NSTAGE], wprep + jt * W_CHUNK,
                        (jt >> 3) ? inB : inA, n, (jt & 7) * 8, y0, tid);
        }

        if (cvtHalf0 && it < 8)
            compute_chunk<true >(patB[p], wsmB[p], w, qid, q, wtbase, acc);
        else
            compute_chunk<false>(patB[p], wsmB[p], w, qid, q, wtbase, acc);

        if (it < 14)
            asm volatile("cp.async.wait_group 1;" ::: "memory");  // it+1 resident
        else
            asm volatile("cp.async.wait_group 0;" ::: "memory");
        __syncthreads();
    }

    // epilogue: bias (bA + cnt*bB), optional residual, relu, optional rounding
    const int gy = y0 + w;
    const float cntf = (float)g_cnt[n];
#pragma unroll
    for (int nt = 0; nt < 8; nt++) {
        const int co = nt * 8 + 2 * q;
        const float bias0 = bA[co]     + cntf * bB[co];
        const float bias1 = bA[co + 1] + cntf * bB[co + 1];
#pragma unroll
        for (int mt = 0; mt < 2; mt++) {
            const int xa = mt * 16 + qid;
            const int xc = xa + 8;
            const int o0 = ((n * CCH + co) * HW + gy) * HW;
            float r0 = acc[mt][nt][0] + bias0;
            float r1 = acc[mt][nt][1] + bias1;
            float r2 = acc[mt][nt][2] + bias0;
            float r3 = acc[mt][nt][3] + bias1;
            if (resid) {
                r0 += resid[o0 + xa];
                r1 += resid[o0 + 1024 + xa];
                r2 += resid[o0 + xc];
                r3 += resid[o0 + 1024 + xc];
            }
            r0 = fmaxf(r0, 0.f); r1 = fmaxf(r1, 0.f);
            r2 = fmaxf(r2, 0.f); r3 = fmaxf(r3, 0.f);
            if (roundOut) {
                r0 = __uint_as_float(f2tf32(r0));
                r1 = __uint_as_float(f2tf32(r1));
                r2 = __uint_as_float(f2tf32(r2));
                r3 = __uint_as_float(f2tf32(r3));
            }
            out[o0 + xa]        = r0;
            out[o0 + 1024 + xa] = r1;
            out[o0 + xc]        = r2;
            out[o0 + 1024 + xc] = r3;
        }
    }
}

// ---------------------------------------------------------------------------
extern "C" void kernel_launch(void* const* d_in, const int* in_sizes, int n_in,
                              void* d_out, int out_size) {
    const float* x    = (const float*)d_in[0];
    const float* w_x0 = (const float*)d_in[1];
    const float* b_x0 = (const float*)d_in[2];
    const float* w_n0 = (const float*)d_in[3];
    const float* b_n0 = (const float*)d_in[4];
    const float* w_x1 = (const float*)d_in[5];
    const float* b_x1 = (const float*)d_in[6];
    const float* w_n1 = (const float*)d_in[7];
    const float* b_n1 = (const float*)d_in[8];
    const void*  msk  = d_in[9];
    float* out = (float*)d_out;

    float *xs, *h, *hs;
    uint2* wprep;
    cudaGetSymbolAddress((void**)&xs, g_xs);
    cudaGetSymbolAddress((void**)&h,  g_h);
    cudaGetSymbolAddress((void**)&hs, g_hs);
    cudaGetSymbolAddress((void**)&wprep, g_wprep);

    static bool attr_set = false;
    if (!attr_set) {
        cudaFuncSetAttribute(conv_kernel, cudaFuncAttributeMaxDynamicSharedMemorySize,
                             SMEM_BYTES);
        attr_set = true;
    }

    detect_kernel<<<1, 256>>>(msk);
    build_kernel<<<1, 256>>>(msk);
    prep_weights<<<(WPREP_TOTAL + 255) / 256, 256>>>(w_x0, w_n0, w_x1, w_n1);

    dim3 agrid(NODES, 16);
    dim3 cgrid(4, NIMG);

    // layer 1: x raw (cvt in loop), xs pre-rounded; h stored rounded
    agg_kernel<<<agrid, 256>>>(x, xs);
    conv_kernel<<<cgrid, 256, SMEM_BYTES>>>(x, xs, wprep, b_x0, b_n0,
                                            nullptr, h, 1, 1);

    // layer 2: h, hs pre-rounded (no cvt); out full fp32
    agg_kernel<<<agrid, 256>>>(h, hs);
    conv_kernel<<<cgrid, 256, SMEM_BYTES>>>(h, hs, wprep + 16 * W_CHUNK, b_x1, b_n1,
                                            x, out, 0, 0);
}

// round 6
// speedup vs baseline: 1.1640x; 1.1640x over previous
#include <cuda_runtime.h>
#include <cstdint>

// Problem constants
#define NIMG 256          // B*L
#define CCH  64           // channels
#define HW   32           // height = width
#define IMGSZ (CCH*HW*HW) // 65536 floats per image
#define NODES 256

// Scratch (device globals: allocation-free per harness rules)
__device__ float g_xs[NIMG * IMGSZ];   // aggregated x (tf32-rounded values)
__device__ float g_h [NIMG * IMGSZ];   // hidden (tf32-rounded values)
__device__ float g_hs[NIMG * IMGSZ];   // aggregated hidden (tf32-rounded)
__device__ int   g_nbr[NODES * 8];
__device__ int   g_cnt[NODES];
__device__ int   g_mode;               // 0=u8 mask, 1=u16, 2=u32/f32

// Pre-transformed weights, tf32 bits:
// [chunk32 = layer*16 + half*8 + cc][tap9][qid8][q4][nt pad 10] uint2
#define W_CHUNK  2880                  // uint2 per chunk (9*8*4*10)
#define W_TAP_U4 160                   // uint4 per tap block
#define WPREP_TOTAL (32 * W_CHUNK)
__device__ uint2 g_wprep[WPREP_TOTAL];

// patch layout: [c8][row10][36 floats]; word col 1+gx; halo cols stay zero
#define P_CSTR 360
#define P_RSTR 36
#define P_ELEMS 2880    // floats per buffer
#define SMEM_BYTES (2*P_ELEMS*4 + 2*W_CHUNK*8)   // 69120: 2 CTA/SM safe

__device__ __forceinline__ uint32_t f2tf32(float f) {
    uint32_t u;
    asm("cvt.rna.tf32.f32 %0, %1;" : "=r"(u) : "f"(f));
    return u;
}

__device__ __forceinline__ void cp16(void* s, const void* g) {
    uint32_t sa = (uint32_t)__cvta_generic_to_shared(s);
    asm volatile("cp.async.cg.shared.global [%0], [%1], 16;" :: "r"(sa), "l"(g));
}

__device__ __forceinline__ void cp4(void* s, const void* g) {
    uint32_t sa = (uint32_t)__cvta_generic_to_shared(s);
    asm volatile("cp.async.ca.shared.global [%0], [%1], 4;" :: "r"(sa), "l"(g));
}

__device__ __forceinline__ void mma_tf32(float& d0, float& d1, float& d2, float& d3,
                                         uint32_t a0, uint32_t a1, uint32_t a2, uint32_t a3,
                                         uint32_t b0, uint32_t b1) {
    asm volatile(
        "mma.sync.aligned.m16n8k8.row.col.f32.tf32.tf32.f32 "
        "{%0,%1,%2,%3},{%4,%5,%6,%7},{%8,%9},{%0,%1,%2,%3};"
        : "+f"(d0), "+f"(d1), "+f"(d2), "+f"(d3)
        : "r"(a0), "r"(a1), "r"(a2), "r"(a3), "r"(b0), "r"(b1));
}

// ---------------------------------------------------------------------------
// Mask dtype detection + neighbor list build (unchanged, correct)
// ---------------------------------------------------------------------------
__global__ void detect_kernel(const void* m) {
    __shared__ int bad;
    int row = threadIdx.x;
    if (row == 0) bad = 0;
    __syncthreads();
    {
        const unsigned char* p = (const unsigned char*)m + row * 64;
        int c = 0;
        for (int j = 0; j < 64; j++) c += (p[j] != 0);
        if (c != 4) atomicOr(&bad, 1);
    }
    __syncthreads();
    int ok8 = !bad;
    __syncthreads();
    if (row == 0) bad = 0;
    __syncthreads();
    if (!ok8) {
        const unsigned short* p = (const unsigned short*)m + row * 64;
        int c = 0;
        for (int j = 0; j < 64; j++) c += (p[j] != 0);
        if (c != 4) atomicOr(&bad, 1);
    }
    __syncthreads();
    int ok16 = (!ok8) && (!bad);
    if (row == 0) g_mode = ok8 ? 0 : (ok16 ? 1 : 2);
}

__global__ void build_kernel(const void* m) {
    int row = threadIdx.x;
    if (row >= NODES) return;
    int mode = g_mode;
    int base = (row >> 6) << 6;
    int cnt = 0;
    if (mode == 0) {
        const unsigned char* p = (const unsigned char*)m + row * 64;
        for (int j = 0; j < 64; j++)
            if (p[j]) { if (cnt < 8) g_nbr[row * 8 + cnt] = base + j; cnt++; }
    } else if (mode == 1) {
        const unsigned short* p = (const unsigned short*)m + row * 64;
        for (int j = 0; j < 64; j++)
            if (p[j]) { if (cnt < 8) g_nbr[row * 8 + cnt] = base + j; cnt++; }
    } else {
        const unsigned int* p = (const unsigned int*)m + row * 64;
        for (int j = 0; j < 64; j++)
            if (p[j]) { if (cnt < 8) g_nbr[row * 8 + cnt] = base + j; cnt++; }
    }
    g_cnt[row] = cnt;
}

// ---------------------------------------------------------------------------
// Weight pre-transform into [chunk][tap][qid][q][nt pad10] uint2 layout
// ---------------------------------------------------------------------------
__global__ void prep_weights(const float* __restrict__ w_x0, const float* __restrict__ w_n0,
                             const float* __restrict__ w_x1, const float* __restrict__ w_n1) {
    int e = blockIdx.x * 256 + threadIdx.x;
    if (e >= WPREP_TOTAL) return;
    int nt = e % 10; int t = e / 10;
    int q   = t & 3;  t >>= 2;
    int qid = t & 7;  t >>= 3;
    int tap = t % 9;  t /= 9;        // t = chunk id 0..31
    int cc   = t & 7;
    int half = (t >> 3) & 1;
    int layer = t >> 4;
    const float* w = layer ? (half ? w_n1 : w_x1) : (half ? w_n0 : w_x0);
    uint2 v = make_uint2(0u, 0u);
    if (nt < 8) {
        int co = nt * 8 + qid;
        int cb = cc * 8;
        v.x = f2tf32(w[co * 576 + (cb + q) * 9 + tap]);
        v.y = f2tf32(w[co * 576 + (cb + q + 4) * 9 + tap]);
    }
    g_wprep[e] = v;
}

// ---------------------------------------------------------------------------
// Neighbor aggregation; output rounded to tf32 values (conv A operand ready)
// ---------------------------------------------------------------------------
__global__ void agg_kernel(const float* __restrict__ src, float* __restrict__ dst) {
    int node = blockIdx.x;
    int cnt = g_cnt[node];
    if (cnt > 8) cnt = 8;
    int i0 = blockIdx.y * blockDim.x + threadIdx.x;
    int stride = gridDim.y * blockDim.x;
    const float4* s4 = (const float4*)src;
    float4* d4 = (float4*)dst;
    int nb[8];
    for (int k = 0; k < cnt; k++) nb[k] = g_nbr[node * 8 + k];
    const int n4 = IMGSZ / 4;
    for (int i = i0; i < n4; i += stride) {
        float4 acc = make_float4(0.f, 0.f, 0.f, 0.f);
        for (int k = 0; k < cnt; k++) {
            float4 v = s4[nb[k] * n4 + i];
            acc.x += v.x; acc.y += v.y; acc.z += v.z; acc.w += v.w;
        }
        acc.x = __uint_as_float(f2tf32(acc.x));
        acc.y = __uint_as_float(f2tf32(acc.y));
        acc.z = __uint_as_float(f2tf32(acc.z));
        acc.w = __uint_as_float(f2tf32(acc.w));
        d4[node * n4 + i] = acc;
    }
}

// ---------------------------------------------------------------------------
// Conv: 2-stage cp.async pipeline (R4 structure), templated cvt
// ---------------------------------------------------------------------------
__device__ __forceinline__ void issue_chunk(float* pat, uint4* wdst,
                                            const uint2* __restrict__ wsrc,
                                            const float* __restrict__ inp,
                                            int n, int cb, int y0, int tid) {
    const uint4* ws = (const uint4*)wsrc;
#pragma unroll
    for (int k = 0; k < 6; k++) {
        int idx = tid + k * 256;
        if (idx < W_CHUNK / 2) cp16(wdst + idx, ws + idx);
    }
#pragma unroll
    for (int k = 0; k < 10; k++) {
        int i = tid + k * 256;
        int col = i & 31;
        int r = (i >> 5) % 10;
        int c = i / 320;
        int gy = y0 + r - 1;
        if (gy >= 0 && gy < HW)
            cp4(pat + c * P_CSTR + r * P_RSTR + 1 + col,
                inp + ((n * CCH + c + cb) * HW + gy) * HW + col);
    }
    asm volatile("cp.async.commit_group;" ::: "memory");
}

template <bool CVT>
__device__ __forceinline__ void compute_chunk(const float* __restrict__ pat,
                                              const uint4* __restrict__ wq,
                                              int w, int qid, int q, int wtbase,
                                              float (&acc)[2][8][4]) {
    uint4 bb[2][4];
#pragma unroll
    for (int j = 0; j < 4; j++) bb[0][j] = wq[wtbase + j];

#pragma unroll
    for (int tap = 0; tap < 9; tap++) {
        const int ty = tap / 3, tx = tap % 3;
        const int cur = tap & 1;
        if (tap < 8) {
            const uint4* wn = wq + (tap + 1) * W_TAP_U4 + wtbase;
#pragma unroll
            for (int j = 0; j < 4; j++) bb[1 - cur][j] = wn[j];
        }
        const int ro = (w + ty) * P_RSTR + qid + tx;
        const int blo = q * P_CSTR + ro;
        const int bhi = (q + 4) * P_CSTR + ro;
        uint32_t a[2][4];
#pragma unroll
        for (int mt = 0; mt < 2; mt++) {
            const int xo = mt * 16;
            if (CVT) {
                a[mt][0] = f2tf32(pat[blo + xo]);
                a[mt][1] = f2tf32(pat[blo + xo + 8]);
                a[mt][2] = f2tf32(pat[bhi + xo]);
                a[mt][3] = f2tf32(pat[bhi + xo + 8]);
            } else {
                a[mt][0] = __float_as_uint(pat[blo + xo]);
                a[mt][1] = __float_as_uint(pat[blo + xo + 8]);
                a[mt][2] = __float_as_uint(pat[bhi + xo]);
                a[mt][3] = __float_as_uint(pat[bhi + xo + 8]);
            }
        }
        const uint32_t* b = (const uint32_t*)bb[cur];
#pragma unroll
        for (int mt = 0; mt < 2; mt++)
#pragma unroll
            for (int nt = 0; nt < 8; nt++)
                mma_tf32(acc[mt][nt][0], acc[mt][nt][1],
                         acc[mt][nt][2], acc[mt][nt][3],
                         a[mt][0], a[mt][1], a[mt][2], a[mt][3],
                         b[2 * nt], b[2 * nt + 1]);
    }
}

__global__ __launch_bounds__(256, 2)
void conv_kernel(const float* __restrict__ inA, const float* __restrict__ inB,
                 const uint2* __restrict__ wprep,
                 const float* __restrict__ bA,  const float* __restrict__ bB,
                 const float* __restrict__ resid, float* __restrict__ out,
                 int cvtHalf0, int roundOut) {
    extern __shared__ uint8_t smem[];
    float* patB[2];
    patB[0] = (float*)smem;
    patB[1] = patB[0] + P_ELEMS;
    uint4* wsmB[2];
    wsmB[0] = (uint4*)(patB[1] + P_ELEMS);
    wsmB[1] = wsmB[0] + W_CHUNK / 2;

    const int n = blockIdx.y;
    const int rb = blockIdx.x;
    const int tid = threadIdx.x;
    const int w = tid >> 5;
    const int lane = tid & 31;
    const int qid = lane >> 2;
    const int q = lane & 3;
    const int y0 = rb * 8;

    // zero both patch buffers once (halo cells never overwritten later)
#pragma unroll
    for (int k = 0; k < 23; k++) {
        int i = tid + k * 256;
        if (i < 2 * P_ELEMS) patB[0][i] = 0.f;
    }
    __syncthreads();

    float acc[2][8][4];
#pragma unroll
    for (int mt = 0; mt < 2; mt++)
#pragma unroll
        for (int nt = 0; nt < 8; nt++)
#pragma unroll
            for (int r = 0; r < 4; r++) acc[mt][nt][r] = 0.f;

    // prolog: chunk 0
    issue_chunk(patB[0], wsmB[0], wprep, inA, n, 0, y0, tid);
    asm volatile("cp.async.wait_group 0;" ::: "memory");
    __syncthreads();

    const int wtbase = (qid * 4 + q) * 5;

    for (int it = 0; it < 16; ++it) {
        const int p = it & 1;
        if (it < 15) {
            const int jt = it + 1;
            issue_chunk(patB[1 - p], wsmB[1 - p], wprep + jt * W_CHUNK,
                        (jt >> 3) ? inB : inA, n, (jt & 7) * 8, y0, tid);
        }

        if (cvtHalf0 && it < 8)
            compute_chunk<true >(patB[p], wsmB[p], w, qid, q, wtbase, acc);
        else
            compute_chunk<false>(patB[p], wsmB[p], w, qid, q, wtbase, acc);

        asm volatile("cp.async.wait_group 0;" ::: "memory");
        __syncthreads();
    }

    // epilogue: bias (bA + cnt*bB), optional residual, relu, optional rounding
    const int gy = y0 + w;
    const float cntf = (float)g_cnt[n];
#pragma unroll
    for (int nt = 0; nt < 8; nt++) {
        const int co = nt * 8 + 2 * q;
        const float bias0 = bA[co]     + cntf * bB[co];
        const float bias1 = bA[co + 1] + cntf * bB[co + 1];
#pragma unroll
        for (int mt = 0; mt < 2; mt++) {
            const int xa = mt * 16 + qid;
            const int xc = xa + 8;
            const int o0 = ((n * CCH + co) * HW + gy) * HW;
            float r0 = acc[mt][nt][0] + bias0;
            float r1 = acc[mt][nt][1] + bias1;
            float r2 = acc[mt][nt][2] + bias0;
            float r3 = acc[mt][nt][3] + bias1;
            if (resid) {
                r0 += resid[o0 + xa];
                r1 += resid[o0 + 1024 + xa];
                r2 += resid[o0 + xc];
                r3 += resid[o0 + 1024 + xc];
            }
            r0 = fmaxf(r0, 0.f); r1 = fmaxf(r1, 0.f);
            r2 = fmaxf(r2, 0.f); r3 = fmaxf(r3, 0.f);
            if (roundOut) {
                r0 = __uint_as_float(f2tf32(r0));
                r1 = __uint_as_float(f2tf32(r1));
                r2 = __uint_as_float(f2tf32(r2));
                r3 = __uint_as_float(f2tf32(r3));
            }
            out[o0 + xa]        = r0;
            out[o0 + 1024 + xa] = r1;
            out[o0 + xc]        = r2;
            out[o0 + 1024 + xc] = r3;
        }
    }
}

// ---------------------------------------------------------------------------
extern "C" void kernel_launch(void* const* d_in, const int* in_sizes, int n_in,
                              void* d_out, int out_size) {
    const float* x    = (const float*)d_in[0];
    const float* w_x0 = (const float*)d_in[1];
    const float* b_x0 = (const float*)d_in[2];
    const float* w_n0 = (const float*)d_in[3];
    const float* b_n0 = (const float*)d_in[4];
    const float* w_x1 = (const float*)d_in[5];
    const float* b_x1 = (const float*)d_in[6];
    const float* w_n1 = (const float*)d_in[7];
    const float* b_n1 = (const float*)d_in[8];
    const void*  msk  = d_in[9];
    float* out = (float*)d_out;

    float *xs, *h, *hs;
    uint2* wprep;
    cudaGetSymbolAddress((void**)&xs, g_xs);
    cudaGetSymbolAddress((void**)&h,  g_h);
    cudaGetSymbolAddress((void**)&hs, g_hs);
    cudaGetSymbolAddress((void**)&wprep, g_wprep);

    static bool attr_set = false;
    if (!attr_set) {
        cudaFuncSetAttribute(conv_kernel, cudaFuncAttributeMaxDynamicSharedMemorySize,
                             SMEM_BYTES);
        attr_set = true;
    }

    detect_kernel<<<1, 256>>>(msk);
    build_kernel<<<1, 256>>>(msk);
    prep_weights<<<(WPREP_TOTAL + 255) / 256, 256>>>(w_x0, w_n0, w_x1, w_n1);

    dim3 agrid(NODES, 16);
    dim3 cgrid(4, NIMG);

    // layer 1: x raw (cvt in loop, chunks 0-7), xs pre-rounded; h stored rounded
    agg_kernel<<<agrid, 256>>>(x, xs);
    conv_kernel<<<cgrid, 256, SMEM_BYTES>>>(x, xs, wprep, b_x0, b_n0,
                                            nullptr, h, 1, 1);

    // layer 2: h, hs pre-rounded (no cvt); out full fp32
    agg_kernel<<<agrid, 256>>>(h, hs);
    conv_kernel<<<cgrid, 256, SMEM_BYTES>>>(h, hs, wprep + 16 * W_CHUNK, b_x1, b_n1,
                                            x, out, 0, 0);
}